// round 4
// baseline (speedup 1.0000x reference)
#include <cuda_runtime.h>
#include <math.h>

#define Bn 64
#define Nn 1024
#define Wn 64
#define Rn 4

// ---------------- device scratch (no allocations allowed) ----------------
__device__ float g_ww [Bn*Nn];       // new write weights (B,N)
__device__ float g_fwd[Bn*Rn*Nn];    // fwd_w (B,R,N)
__device__ float g_bwd[Bn*Rn*Nn];    // bwd_w (B,R,N)

__device__ __forceinline__ float softplusf(float x){
    return fmaxf(x, 0.f) + log1pf(expf(-fabsf(x)));
}

// block reduce helpers: require exactly 1024 threads (32 warps)
__device__ __forceinline__ float block_reduce_max(float v, float* s_red, float* s_out,
                                                  int lane, int wid){
#pragma unroll
    for (int o = 16; o; o >>= 1) v = fmaxf(v, __shfl_xor_sync(0xffffffffu, v, o));
    if (lane == 0) s_red[wid] = v;
    __syncthreads();
    if (wid == 0){
        float t = s_red[lane];
#pragma unroll
        for (int o = 16; o; o >>= 1) t = fmaxf(t, __shfl_xor_sync(0xffffffffu, t, o));
        if (lane == 0) *s_out = t;
    }
    __syncthreads();
    return *s_out;
}

__device__ __forceinline__ float block_reduce_sum(float v, float* s_red, float* s_out,
                                                  int lane, int wid){
#pragma unroll
    for (int o = 16; o; o >>= 1) v += __shfl_xor_sync(0xffffffffu, v, o);
    if (lane == 0) s_red[wid] = v;
    __syncthreads();
    if (wid == 0){
        float t = s_red[lane];
#pragma unroll
        for (int o = 16; o; o >>= 1) t += __shfl_xor_sync(0xffffffffu, t, o);
        if (lane == 0) *s_out = t;
    }
    __syncthreads();
    return *s_out;
}

// ============================================================================
// K1: usage, write content (cosine softmax), allocation (sort+scan),
//     write_weights -> g_ww; zero g_fwd/g_bwd.
// One block per batch, 1024 threads.
// ============================================================================
__global__ void __launch_bounds__(1024) k1_kernel(
    const float* __restrict__ memory,      // (B,N,W)
    const float* __restrict__ prw,         // (B,R,N)
    const float* __restrict__ pww,         // (B,1,N)
    const float* __restrict__ pusage,      // (B,N)
    const float* __restrict__ wkeys,       // (B,1,W)
    const float* __restrict__ wstr,        // (B,1)
    const float* __restrict__ fgate,       // (B,R)
    const float* __restrict__ agate,       // (B,1)
    const float* __restrict__ wgate)       // (B,1)
{
    int b   = blockIdx.x;
    int tid = threadIdx.x;
    int lane = tid & 31, wid = tid >> 5;

    __shared__ float s_usage[Nn];
    __shared__ float s_sharp[Nn];   // sharp similarities, later reused as alloc
    __shared__ float s_val[Nn];
    __shared__ int   s_idx[Nn];
    __shared__ float s_scan[Nn];
    __shared__ float s_red[32];
    __shared__ float s_b0, s_b1;

    // ---- usage ----
    {
        float pu = pusage[b*Nn + tid];
        float w0 = pww[b*Nn + tid];
        float u  = pu + (1.f - pu) * w0;        // NW=1: agg_write == pww
        float phi = 1.f;
#pragma unroll
        for (int r = 0; r < Rn; r++){
            float fg = fgate[b*Rn + r];
            phi *= 1.f - fg * prw[(b*Rn + r)*Nn + tid];
        }
        s_usage[tid] = u * phi;
    }

    // ---- write content: cosine similarity, warp per row ----
    float2 key = *(const float2*)(wkeys + b*Wn + lane*2);
    float kn = key.x*key.x + key.y*key.y;
#pragma unroll
    for (int o = 16; o; o >>= 1) kn += __shfl_xor_sync(0xffffffffu, kn, o);
    kn = sqrtf(kn + 1e-6f);
    float sp = softplusf(wstr[b]);

    for (int n = wid; n < Nn; n += 32){
        float2 m = ((const float2*)(memory + ((size_t)(b*Nn + n))*Wn))[lane];
        float d = key.x*m.x + key.y*m.y;
        float q = m.x*m.x + m.y*m.y;
#pragma unroll
        for (int o = 16; o; o >>= 1){
            d += __shfl_xor_sync(0xffffffffu, d, o);
            q += __shfl_xor_sync(0xffffffffu, q, o);
        }
        if (lane == 0){
            float mnorm = sqrtf(q + 1e-6f);
            s_sharp[n] = d / (kn * mnorm + 1e-6f) * sp;
        }
    }
    __syncthreads();

    // ---- softmax over N ----
    float v  = s_sharp[tid];
    float mx = block_reduce_max(v, s_red, &s_b0, lane, wid);
    float e  = expf(v - mx);
    float sm = block_reduce_sum(e, s_red, &s_b1, lane, wid);
    float content = e / sm;

    // ---- allocation: bitonic sort of nonusage (desc, tie-break asc index) ----
    float usage = s_usage[tid];
    float up   = 1e-6f + (1.f - 1e-6f) * usage;
    float nonu = 1.f - up;
    s_val[tid] = nonu;
    s_idx[tid] = tid;
    __syncthreads();
    for (int k = 2; k <= Nn; k <<= 1){
        for (int j = k >> 1; j > 0; j >>= 1){
            int ixj = tid ^ j;
            if (ixj > tid){
                float a = s_val[tid], c = s_val[ixj];
                int   ia = s_idx[tid], ic = s_idx[ixj];
                bool less = (a < c) || (a == c && ia > ic);
                bool doswap = ((tid & k) == 0) ? less : !less;
                if (doswap){
                    s_val[tid] = c; s_val[ixj] = a;
                    s_idx[tid] = ic; s_idx[ixj] = ia;
                }
            }
            __syncthreads();
        }
    }
    // inclusive product scan of sorted_usage (Hillis-Steele)
    float snon = s_val[tid];
    s_scan[tid] = 1.f - snon;
    __syncthreads();
    for (int off = 1; off < Nn; off <<= 1){
        float t = (tid >= off) ? s_scan[tid - off] : 1.f;
        __syncthreads();
        if (tid >= off) s_scan[tid] *= t;
        __syncthreads();
    }
    float pexcl = (tid == 0) ? 1.f : s_scan[tid - 1];
    float salloc = snon * pexcl;
    int dest = s_idx[tid];
    __syncthreads();           // everyone done reading s_sharp (content in regs)
    s_sharp[dest] = salloc;    // scatter alloc back
    __syncthreads();
    float alloc = s_sharp[tid];

    // ---- write weights ----
    float ag = agate[b], wg = wgate[b];
    float wwn = wg * (ag * alloc + (1.f - ag) * content);
    g_ww[b*Nn + tid] = wwn;

    // zero fwd/bwd scratch for this batch
    for (int i = tid; i < Rn*Nn; i += 1024){
        g_fwd[b*Rn*Nn + i] = 0.f;
        g_bwd[b*Rn*Nn + i] = 0.f;
    }
}

// ============================================================================
// K2: fused link update + fwd/bwd contractions.
//   L[n][m] = (n!=m) * ((1-ww[n]-ww[m])*prev_link[n][m] + ww[n]*prec[m])
//   fwd[r][n] = sum_m prw[r][m]*L[n][m]   (row reduce, shuffle+smem, no atomics)
//   bwd[r][m] = sum_n prw[r][n]*L[n][m]   (thread-local regs, atomicAdd at end)
// grid (16 row-tiles, 64 batches) x 256 threads; thread owns 4 columns.
// ============================================================================
__global__ void __launch_bounds__(256) k2_kernel(
    const float* __restrict__ link,    // (B,1,N,N)
    const float* __restrict__ prw,     // (B,R,N)
    const float* __restrict__ prec)    // (B,1,N)
{
    int b  = blockIdx.y;
    int n0 = blockIdx.x * 64;
    int t  = threadIdx.x;
    int lane = t & 31, wid = t >> 5;

    __shared__ float4 s_prw[Nn];     // [n] -> prw[0..3][n]
    __shared__ float  s_ww [Nn];
    __shared__ float  s_fwd[64][32]; // [row_local][r*8 + warp]

    for (int i = t; i < Nn; i += 256){
        float4 p;
        p.x = prw[(b*Rn + 0)*Nn + i];
        p.y = prw[(b*Rn + 1)*Nn + i];
        p.z = prw[(b*Rn + 2)*Nn + i];
        p.w = prw[(b*Rn + 3)*Nn + i];
        s_prw[i] = p;
        s_ww[i]  = g_ww[b*Nn + i];
    }
    __syncthreads();

    int m0 = t * 4;
    // hoisted per-column constants
    float wwm[4], pcmv[4], pjm[4][4];   // pjm[j][r] = prw[r][m0+j]
#pragma unroll
    for (int j = 0; j < 4; j++){
        wwm[j] = s_ww[m0 + j];
        float4 pj = s_prw[m0 + j];
        pjm[j][0] = pj.x; pjm[j][1] = pj.y; pjm[j][2] = pj.z; pjm[j][3] = pj.w;
    }
    {
        float4 pc = *(const float4*)(prec + b*Nn + m0);
        pcmv[0] = pc.x; pcmv[1] = pc.y; pcmv[2] = pc.z; pcmv[3] = pc.w;
    }

    float bacc[4][4];
#pragma unroll
    for (int r = 0; r < 4; r++)
#pragma unroll
        for (int j = 0; j < 4; j++) bacc[r][j] = 0.f;

    const float* Lb = link + (size_t)b * Nn * Nn;

#pragma unroll 2
    for (int n = n0; n < n0 + 64; n++){
        float wn = s_ww[n];
        float cn = 1.f - wn;
        float4 pn = s_prw[n];
        float pnr[4] = {pn.x, pn.y, pn.z, pn.w};

        float4 P = *(const float4*)(Lb + (size_t)n * Nn + m0);
        float Pv[4] = {P.x, P.y, P.z, P.w};

        float lk[4];
#pragma unroll
        for (int j = 0; j < 4; j++)
            lk[j] = fmaf(cn - wwm[j], Pv[j], wn * pcmv[j]);
#pragma unroll
        for (int j = 0; j < 4; j++)
            if (n == m0 + j) lk[j] = 0.f;   // zero diagonal

        // fwd partials for this row
        float fr[4];
#pragma unroll
        for (int r = 0; r < 4; r++){
            float f = 0.f;
#pragma unroll
            for (int j = 0; j < 4; j++) f = fmaf(pjm[j][r], lk[j], f);
            fr[r] = f;
        }
#pragma unroll
        for (int o = 16; o; o >>= 1){
            fr[0] += __shfl_xor_sync(0xffffffffu, fr[0], o);
            fr[1] += __shfl_xor_sync(0xffffffffu, fr[1], o);
            fr[2] += __shfl_xor_sync(0xffffffffu, fr[2], o);
            fr[3] += __shfl_xor_sync(0xffffffffu, fr[3], o);
        }
        if (lane == 0){
            int nl = n - n0;
            s_fwd[nl][0*8 + wid] = fr[0];
            s_fwd[nl][1*8 + wid] = fr[1];
            s_fwd[nl][2*8 + wid] = fr[2];
            s_fwd[nl][3*8 + wid] = fr[3];
        }

        // bwd accumulation (thread-local over rows)
#pragma unroll
        for (int r = 0; r < 4; r++)
#pragma unroll
            for (int j = 0; j < 4; j++)
                bacc[r][j] = fmaf(pnr[r], lk[j], bacc[r][j]);
    }
    __syncthreads();

    // fwd final: one thread per (row_local, r)
    {
        int nl = t >> 2, r = t & 3;
        float s = 0.f;
#pragma unroll
        for (int w = 0; w < 8; w++) s += s_fwd[nl][r*8 + w];
        g_fwd[(b*Rn + r)*Nn + n0 + nl] = s;
    }

    // bwd: atomic add (16 tiles contend per address)
    float* bw = g_bwd + (size_t)b * Rn * Nn;
#pragma unroll
    for (int r = 0; r < 4; r++)
#pragma unroll
        for (int j = 0; j < 4; j++)
            atomicAdd(&bw[r*Nn + m0 + j], bacc[r][j]);
}

// ============================================================================
// K3: memory_new (on the fly), read content cosine softmax, read mode softmax,
//     read weights, read words. One block per batch, 1024 threads.
//     read_words = G - e*H + wv*S with
//       G[r][k] = sum_n rw[r][n]*mem[n][k]
//       H[r][k] = sum_n (rw[r][n]*ww[n])*mem[n][k]
//       S[r]    = sum_n rw[r][n]*ww[n]
// ============================================================================
__global__ void __launch_bounds__(1024) k3_kernel(
    const float* __restrict__ memory,   // (B,N,W)
    const float* __restrict__ rkeys,    // (B,R,W)
    const float* __restrict__ rstr,     // (B,R)
    const float* __restrict__ wvec,     // (B,1,W)
    const float* __restrict__ evec,     // (B,1,W)
    const float* __restrict__ rmode,    // (B,R,3)
    float* __restrict__ out)            // (B,R,W)
{
    int b   = blockIdx.x;
    int tid = threadIdx.x;
    int lane = tid & 31, wid = tid >> 5;

    __shared__ float  s_rw[Rn][Nn];   // sharp -> read_weights (16KB)
    __shared__ float  s_ww[Nn];
    __shared__ float  s_red[32];
    __shared__ float  s_b0, s_b1;
    __shared__ float2 s_G[8][Rn][32];
    __shared__ float2 s_H[8][Rn][32];
    __shared__ float  s_S[8][Rn];

    s_ww[tid] = g_ww[b*Nn + tid];
    __syncthreads();

    // per-lane key / vector registers
    float2 k0 = *(const float2*)(rkeys + (b*Rn + 0)*Wn + lane*2);
    float2 k1 = *(const float2*)(rkeys + (b*Rn + 1)*Wn + lane*2);
    float2 k2 = *(const float2*)(rkeys + (b*Rn + 2)*Wn + lane*2);
    float2 k3 = *(const float2*)(rkeys + (b*Rn + 3)*Wn + lane*2);
    float2 ev = *(const float2*)(evec + b*Wn + lane*2);
    float2 wv = *(const float2*)(wvec + b*Wn + lane*2);

    float q0 = k0.x*k0.x + k0.y*k0.y;
    float q1 = k1.x*k1.x + k1.y*k1.y;
    float q2 = k2.x*k2.x + k2.y*k2.y;
    float q3 = k3.x*k3.x + k3.y*k3.y;
#pragma unroll
    for (int o = 16; o; o >>= 1){
        q0 += __shfl_xor_sync(0xffffffffu, q0, o);
        q1 += __shfl_xor_sync(0xffffffffu, q1, o);
        q2 += __shfl_xor_sync(0xffffffffu, q2, o);
        q3 += __shfl_xor_sync(0xffffffffu, q3, o);
    }
    float kn0 = sqrtf(q0 + 1e-6f), kn1 = sqrtf(q1 + 1e-6f);
    float kn2 = sqrtf(q2 + 1e-6f), kn3 = sqrtf(q3 + 1e-6f);
    float sp0 = softplusf(rstr[b*Rn + 0]);
    float sp1 = softplusf(rstr[b*Rn + 1]);
    float sp2 = softplusf(rstr[b*Rn + 2]);
    float sp3 = softplusf(rstr[b*Rn + 3]);

    // phase A: sharp[r][n] from memory_new rows (warp per row)
    for (int n = wid; n < Nn; n += 32){
        float2 m = ((const float2*)(memory + ((size_t)(b*Nn + n))*Wn))[lane];
        float w = s_ww[n];
        float2 mn;
        mn.x = fmaf(m.x, 1.f - w*ev.x, w*wv.x);
        mn.y = fmaf(m.y, 1.f - w*ev.y, w*wv.y);
        float d0 = mn.x*k0.x + mn.y*k0.y;
        float d1 = mn.x*k1.x + mn.y*k1.y;
        float d2 = mn.x*k2.x + mn.y*k2.y;
        float d3 = mn.x*k3.x + mn.y*k3.y;
        float qq = mn.x*mn.x + mn.y*mn.y;
#pragma unroll
        for (int o = 16; o; o >>= 1){
            d0 += __shfl_xor_sync(0xffffffffu, d0, o);
            d1 += __shfl_xor_sync(0xffffffffu, d1, o);
            d2 += __shfl_xor_sync(0xffffffffu, d2, o);
            d3 += __shfl_xor_sync(0xffffffffu, d3, o);
            qq += __shfl_xor_sync(0xffffffffu, qq, o);
        }
        if (lane == 0){
            float mnorm = sqrtf(qq + 1e-6f);
            s_rw[0][n] = d0 / (kn0 * mnorm + 1e-6f) * sp0;
            s_rw[1][n] = d1 / (kn1 * mnorm + 1e-6f) * sp1;
            s_rw[2][n] = d2 / (kn2 * mnorm + 1e-6f) * sp2;
            s_rw[3][n] = d3 / (kn3 * mnorm + 1e-6f) * sp3;
        }
    }
    __syncthreads();

    // phase B: softmax per r + combine with fwd/bwd via read-mode softmax
    for (int r = 0; r < Rn; r++){
        float v  = s_rw[r][tid];
        float mx = block_reduce_max(v, s_red, &s_b0, lane, wid);
        float e  = expf(v - mx);
        float sm = block_reduce_sum(e, s_red, &s_b1, lane, wid);
        float rc = e / sm;

        float m0v = rmode[(b*Rn + r)*3 + 0];
        float m1v = rmode[(b*Rn + r)*3 + 1];
        float m2v = rmode[(b*Rn + r)*3 + 2];
        float mm = fmaxf(m0v, fmaxf(m1v, m2v));
        float e0 = expf(m0v - mm), e1 = expf(m1v - mm), e2 = expf(m2v - mm);
        float inv = 1.f / (e0 + e1 + e2);
        float bm = e0 * inv, fm = e1 * inv, cm = e2 * inv;

        float rw = cm * rc
                 + fm * g_fwd[(b*Rn + r)*Nn + tid]
                 + bm * g_bwd[(b*Rn + r)*Nn + tid];
        s_rw[r][tid] = rw;
    }
    __syncthreads();

    // phase C: read words
    {
        int z  = tid >> 7;          // 0..7 (splits N)
        int r  = (tid >> 5) & 3;    // 0..3
        int kh = tid & 31;          // 0..31 -> k = 2*kh
        const float* mp = memory + (size_t)(b*Nn)*Wn + kh*2;
        float2 G = make_float2(0.f, 0.f);
        float2 H = make_float2(0.f, 0.f);
        float  S = 0.f;
        int nbase = z * 128;
#pragma unroll 4
        for (int i = 0; i < 128; i++){
            int n = nbase + i;
            float2 m = *(const float2*)(mp + (size_t)n * Wn);
            float rwv = s_rw[r][n];
            float w   = s_ww[n];
            float t2  = rwv * w;
            G.x = fmaf(rwv, m.x, G.x); G.y = fmaf(rwv, m.y, G.y);
            H.x = fmaf(t2,  m.x, H.x); H.y = fmaf(t2,  m.y, H.y);
            S += t2;
        }
        s_G[z][r][kh] = G;
        s_H[z][r][kh] = H;
        if (kh == 0) s_S[z][r] = S;
    }
    __syncthreads();
    if (tid < 128){
        int r2 = tid >> 5, kh2 = tid & 31;
        float gx = 0.f, gy = 0.f, hx = 0.f, hy = 0.f, s = 0.f;
#pragma unroll
        for (int zz = 0; zz < 8; zz++){
            float2 g = s_G[zz][r2][kh2]; gx += g.x; gy += g.y;
            float2 h = s_H[zz][r2][kh2]; hx += h.x; hy += h.y;
            s += s_S[zz][r2];
        }
        float2 e = *(const float2*)(evec + b*Wn + kh2*2);
        float2 w = *(const float2*)(wvec + b*Wn + kh2*2);
        out[(b*Rn + r2)*Wn + kh2*2    ] = gx - e.x*hx + w.x*s;
        out[(b*Rn + r2)*Wn + kh2*2 + 1] = gy - e.y*hy + w.y*s;
    }
}

// ============================================================================
extern "C" void kernel_launch(void* const* d_in, const int* in_sizes, int n_in,
                              void* d_out, int out_size)
{
    const float* memory  = (const float*)d_in[0];
    const float* prw     = (const float*)d_in[1];
    const float* pww     = (const float*)d_in[2];
    const float* pusage  = (const float*)d_in[3];
    const float* plink   = (const float*)d_in[4];
    const float* pprec   = (const float*)d_in[5];
    const float* rkeys   = (const float*)d_in[6];
    const float* rstr    = (const float*)d_in[7];
    const float* wkeys   = (const float*)d_in[8];
    const float* wstr    = (const float*)d_in[9];
    const float* wvec    = (const float*)d_in[10];
    const float* evec    = (const float*)d_in[11];
    const float* fgate   = (const float*)d_in[12];
    const float* agate   = (const float*)d_in[13];
    const float* wgate   = (const float*)d_in[14];
    const float* rmode   = (const float*)d_in[15];
    float* out = (float*)d_out;

    k1_kernel<<<Bn, 1024>>>(memory, prw, pww, pusage, wkeys, wstr,
                            fgate, agate, wgate);
    k2_kernel<<<dim3(16, Bn), 256>>>(plink, prw, pprec);
    k3_kernel<<<Bn, 1024>>>(memory, rkeys, rstr, wvec, evec, rmode, out);
}

// round 5
// speedup vs baseline: 1.0122x; 1.0122x over previous
#include <cuda_runtime.h>
#include <math.h>

#define Bn 64
#define Nn 1024
#define Wn 64
#define Rn 4

// ---------------- device scratch (no allocations allowed) ----------------
__device__ float g_ww [Bn*Nn];       // new write weights (B,N)
__device__ float g_fwd[Bn*Rn*Nn];    // fwd_w (B,R,N)
__device__ float g_bwd[Bn*Rn*Nn];    // bwd_w (B,R,N)

__device__ __forceinline__ float softplusf(float x){
    return fmaxf(x, 0.f) + log1pf(expf(-fabsf(x)));
}

// block reduce helpers: require exactly 1024 threads (32 warps)
__device__ __forceinline__ float block_reduce_max(float v, float* s_red, float* s_out,
                                                  int lane, int wid){
#pragma unroll
    for (int o = 16; o; o >>= 1) v = fmaxf(v, __shfl_xor_sync(0xffffffffu, v, o));
    if (lane == 0) s_red[wid] = v;
    __syncthreads();
    if (wid == 0){
        float t = s_red[lane];
#pragma unroll
        for (int o = 16; o; o >>= 1) t = fmaxf(t, __shfl_xor_sync(0xffffffffu, t, o));
        if (lane == 0) *s_out = t;
    }
    __syncthreads();
    return *s_out;
}

__device__ __forceinline__ float block_reduce_sum(float v, float* s_red, float* s_out,
                                                  int lane, int wid){
#pragma unroll
    for (int o = 16; o; o >>= 1) v += __shfl_xor_sync(0xffffffffu, v, o);
    if (lane == 0) s_red[wid] = v;
    __syncthreads();
    if (wid == 0){
        float t = s_red[lane];
#pragma unroll
        for (int o = 16; o; o >>= 1) t += __shfl_xor_sync(0xffffffffu, t, o);
        if (lane == 0) *s_out = t;
    }
    __syncthreads();
    return *s_out;
}

// ============================================================================
// K1: usage, write content (cosine softmax), allocation (sort+scan),
//     write_weights -> g_ww; zero g_fwd/g_bwd.
// One block per batch, 1024 threads.
// ============================================================================
__global__ void __launch_bounds__(1024) k1_kernel(
    const float* __restrict__ memory,      // (B,N,W)
    const float* __restrict__ prw,         // (B,R,N)
    const float* __restrict__ pww,         // (B,1,N)
    const float* __restrict__ pusage,      // (B,N)
    const float* __restrict__ wkeys,       // (B,1,W)
    const float* __restrict__ wstr,        // (B,1)
    const float* __restrict__ fgate,       // (B,R)
    const float* __restrict__ agate,       // (B,1)
    const float* __restrict__ wgate)       // (B,1)
{
    int b   = blockIdx.x;
    int tid = threadIdx.x;
    int lane = tid & 31, wid = tid >> 5;

    __shared__ float s_usage[Nn];
    __shared__ float s_sharp[Nn];   // sharp similarities, later reused as alloc
    __shared__ float s_val[Nn];
    __shared__ int   s_idx[Nn];
    __shared__ float s_scan[Nn];
    __shared__ float s_red[32];
    __shared__ float s_b0, s_b1;

    // ---- usage ----
    {
        float pu = pusage[b*Nn + tid];
        float w0 = pww[b*Nn + tid];
        float u  = pu + (1.f - pu) * w0;        // NW=1: agg_write == pww
        float phi = 1.f;
#pragma unroll
        for (int r = 0; r < Rn; r++){
            float fg = fgate[b*Rn + r];
            phi *= 1.f - fg * prw[(b*Rn + r)*Nn + tid];
        }
        s_usage[tid] = u * phi;
    }

    // ---- write content: cosine similarity, warp per row ----
    float2 key = *(const float2*)(wkeys + b*Wn + lane*2);
    float kn = key.x*key.x + key.y*key.y;
#pragma unroll
    for (int o = 16; o; o >>= 1) kn += __shfl_xor_sync(0xffffffffu, kn, o);
    kn = sqrtf(kn + 1e-6f);
    float sp = softplusf(wstr[b]);

    for (int n = wid; n < Nn; n += 32){
        float2 m = ((const float2*)(memory + ((size_t)(b*Nn + n))*Wn))[lane];
        float d = key.x*m.x + key.y*m.y;
        float q = m.x*m.x + m.y*m.y;
#pragma unroll
        for (int o = 16; o; o >>= 1){
            d += __shfl_xor_sync(0xffffffffu, d, o);
            q += __shfl_xor_sync(0xffffffffu, q, o);
        }
        if (lane == 0){
            float mnorm = sqrtf(q + 1e-6f);
            s_sharp[n] = d / (kn * mnorm + 1e-6f) * sp;
        }
    }
    __syncthreads();

    // ---- softmax over N ----
    float v  = s_sharp[tid];
    float mx = block_reduce_max(v, s_red, &s_b0, lane, wid);
    float e  = expf(v - mx);
    float sm = block_reduce_sum(e, s_red, &s_b1, lane, wid);
    float content = e / sm;

    // ---- allocation: bitonic sort of nonusage (desc, tie-break asc index) ----
    float usage = s_usage[tid];
    float up   = 1e-6f + (1.f - 1e-6f) * usage;
    float nonu = 1.f - up;
    s_val[tid] = nonu;
    s_idx[tid] = tid;
    __syncthreads();
    for (int k = 2; k <= Nn; k <<= 1){
        for (int j = k >> 1; j > 0; j >>= 1){
            int ixj = tid ^ j;
            if (ixj > tid){
                float a = s_val[tid], c = s_val[ixj];
                int   ia = s_idx[tid], ic = s_idx[ixj];
                bool less = (a < c) || (a == c && ia > ic);
                bool doswap = ((tid & k) == 0) ? less : !less;
                if (doswap){
                    s_val[tid] = c; s_val[ixj] = a;
                    s_idx[tid] = ic; s_idx[ixj] = ia;
                }
            }
            __syncthreads();
        }
    }
    // inclusive product scan of sorted_usage (Hillis-Steele)
    float snon = s_val[tid];
    s_scan[tid] = 1.f - snon;
    __syncthreads();
    for (int off = 1; off < Nn; off <<= 1){
        float t = (tid >= off) ? s_scan[tid - off] : 1.f;
        __syncthreads();
        if (tid >= off) s_scan[tid] *= t;
        __syncthreads();
    }
    float pexcl = (tid == 0) ? 1.f : s_scan[tid - 1];
    float salloc = snon * pexcl;
    int dest = s_idx[tid];
    __syncthreads();           // everyone done reading s_sharp (content in regs)
    s_sharp[dest] = salloc;    // scatter alloc back
    __syncthreads();
    float alloc = s_sharp[tid];

    // ---- write weights ----
    float ag = agate[b], wg = wgate[b];
    float wwn = wg * (ag * alloc + (1.f - ag) * content);
    g_ww[b*Nn + tid] = wwn;

    // zero fwd/bwd scratch for this batch
    for (int i = tid; i < Rn*Nn; i += 1024){
        g_fwd[b*Rn*Nn + i] = 0.f;
        g_bwd[b*Rn*Nn + i] = 0.f;
    }
}

// ============================================================================
// K2: fused link update + fwd/bwd contractions.
//   L[n][m] = (n!=m) * ((1-ww[n]-ww[m])*prev_link[n][m] + ww[n]*prec[m])
//   fwd[r][n] = sum_m prw[r][m]*L[n][m]   (row reduce, shuffle+smem, no atomics)
//   bwd[r][m] = sum_n prw[r][n]*L[n][m]   (thread-local regs, atomicAdd at end)
// grid (16 row-tiles, 64 batches) x 256 threads; thread owns 4 columns.
// ============================================================================
__global__ void __launch_bounds__(256) k2_kernel(
    const float* __restrict__ link,    // (B,1,N,N)
    const float* __restrict__ prw,     // (B,R,N)
    const float* __restrict__ prec)    // (B,1,N)
{
    int b  = blockIdx.y;
    int n0 = blockIdx.x * 64;
    int t  = threadIdx.x;
    int lane = t & 31, wid = t >> 5;

    __shared__ float4 s_prw[Nn];     // [n] -> prw[0..3][n]
    __shared__ float  s_ww [Nn];
    __shared__ float  s_fwd[64][32]; // [row_local][r*8 + warp]

    for (int i = t; i < Nn; i += 256){
        float4 p;
        p.x = prw[(b*Rn + 0)*Nn + i];
        p.y = prw[(b*Rn + 1)*Nn + i];
        p.z = prw[(b*Rn + 2)*Nn + i];
        p.w = prw[(b*Rn + 3)*Nn + i];
        s_prw[i] = p;
        s_ww[i]  = g_ww[b*Nn + i];
    }
    __syncthreads();

    int m0 = t * 4;
    // hoisted per-column constants
    float wwm[4], pcmv[4], pjm[4][4];   // pjm[j][r] = prw[r][m0+j]
#pragma unroll
    for (int j = 0; j < 4; j++){
        wwm[j] = s_ww[m0 + j];
        float4 pj = s_prw[m0 + j];
        pjm[j][0] = pj.x; pjm[j][1] = pj.y; pjm[j][2] = pj.z; pjm[j][3] = pj.w;
    }
    {
        float4 pc = *(const float4*)(prec + b*Nn + m0);
        pcmv[0] = pc.x; pcmv[1] = pc.y; pcmv[2] = pc.z; pcmv[3] = pc.w;
    }

    float bacc[4][4];
#pragma unroll
    for (int r = 0; r < 4; r++)
#pragma unroll
        for (int j = 0; j < 4; j++) bacc[r][j] = 0.f;

    const float* Lb = link + (size_t)b * Nn * Nn;

#pragma unroll 2
    for (int n = n0; n < n0 + 64; n++){
        float wn = s_ww[n];
        float cn = 1.f - wn;
        float4 pn = s_prw[n];
        float pnr[4] = {pn.x, pn.y, pn.z, pn.w};

        float4 P = *(const float4*)(Lb + (size_t)n * Nn + m0);
        float Pv[4] = {P.x, P.y, P.z, P.w};

        float lk[4];
#pragma unroll
        for (int j = 0; j < 4; j++)
            lk[j] = fmaf(cn - wwm[j], Pv[j], wn * pcmv[j]);
#pragma unroll
        for (int j = 0; j < 4; j++)
            if (n == m0 + j) lk[j] = 0.f;   // zero diagonal

        // fwd partials for this row
        float fr[4];
#pragma unroll
        for (int r = 0; r < 4; r++){
            float f = 0.f;
#pragma unroll
            for (int j = 0; j < 4; j++) f = fmaf(pjm[j][r], lk[j], f);
            fr[r] = f;
        }
#pragma unroll
        for (int o = 16; o; o >>= 1){
            fr[0] += __shfl_xor_sync(0xffffffffu, fr[0], o);
            fr[1] += __shfl_xor_sync(0xffffffffu, fr[1], o);
            fr[2] += __shfl_xor_sync(0xffffffffu, fr[2], o);
            fr[3] += __shfl_xor_sync(0xffffffffu, fr[3], o);
        }
        if (lane == 0){
            int nl = n - n0;
            s_fwd[nl][0*8 + wid] = fr[0];
            s_fwd[nl][1*8 + wid] = fr[1];
            s_fwd[nl][2*8 + wid] = fr[2];
            s_fwd[nl][3*8 + wid] = fr[3];
        }

        // bwd accumulation (thread-local over rows)
#pragma unroll
        for (int r = 0; r < 4; r++)
#pragma unroll
            for (int j = 0; j < 4; j++)
                bacc[r][j] = fmaf(pnr[r], lk[j], bacc[r][j]);
    }
    __syncthreads();

    // fwd final: one thread per (row_local, r)
    {
        int nl = t >> 2, r = t & 3;
        float s = 0.f;
#pragma unroll
        for (int w = 0; w < 8; w++) s += s_fwd[nl][r*8 + w];
        g_fwd[(b*Rn + r)*Nn + n0 + nl] = s;
    }

    // bwd: atomic add (16 tiles contend per address)
    float* bw = g_bwd + (size_t)b * Rn * Nn;
#pragma unroll
    for (int r = 0; r < 4; r++)
#pragma unroll
        for (int j = 0; j < 4; j++)
            atomicAdd(&bw[r*Nn + m0 + j], bacc[r][j]);
}

// ============================================================================
// K3: memory_new (on the fly), read content cosine softmax, read mode softmax,
//     read weights, read words. One block per batch, 1024 threads.
//     read_words = G - e*H + wv*S with
//       G[r][k] = sum_n rw[r][n]*mem[n][k]
//       H[r][k] = sum_n (rw[r][n]*ww[n])*mem[n][k]
//       S[r]    = sum_n rw[r][n]*ww[n]
// ============================================================================
__global__ void __launch_bounds__(1024) k3_kernel(
    const float* __restrict__ memory,   // (B,N,W)
    const float* __restrict__ rkeys,    // (B,R,W)
    const float* __restrict__ rstr,     // (B,R)
    const float* __restrict__ wvec,     // (B,1,W)
    const float* __restrict__ evec,     // (B,1,W)
    const float* __restrict__ rmode,    // (B,R,3)
    float* __restrict__ out)            // (B,R,W)
{
    int b   = blockIdx.x;
    int tid = threadIdx.x;
    int lane = tid & 31, wid = tid >> 5;

    __shared__ float  s_rw[Rn][Nn];   // sharp -> read_weights (16KB)
    __shared__ float  s_ww[Nn];
    __shared__ float  s_red[32];
    __shared__ float  s_b0, s_b1;
    __shared__ float2 s_G[8][Rn][32];
    __shared__ float2 s_H[8][Rn][32];
    __shared__ float  s_S[8][Rn];

    s_ww[tid] = g_ww[b*Nn + tid];
    __syncthreads();

    // per-lane key / vector registers
    float2 k0 = *(const float2*)(rkeys + (b*Rn + 0)*Wn + lane*2);
    float2 k1 = *(const float2*)(rkeys + (b*Rn + 1)*Wn + lane*2);
    float2 k2 = *(const float2*)(rkeys + (b*Rn + 2)*Wn + lane*2);
    float2 k3 = *(const float2*)(rkeys + (b*Rn + 3)*Wn + lane*2);
    float2 ev = *(const float2*)(evec + b*Wn + lane*2);
    float2 wv = *(const float2*)(wvec + b*Wn + lane*2);

    float q0 = k0.x*k0.x + k0.y*k0.y;
    float q1 = k1.x*k1.x + k1.y*k1.y;
    float q2 = k2.x*k2.x + k2.y*k2.y;
    float q3 = k3.x*k3.x + k3.y*k3.y;
#pragma unroll
    for (int o = 16; o; o >>= 1){
        q0 += __shfl_xor_sync(0xffffffffu, q0, o);
        q1 += __shfl_xor_sync(0xffffffffu, q1, o);
        q2 += __shfl_xor_sync(0xffffffffu, q2, o);
        q3 += __shfl_xor_sync(0xffffffffu, q3, o);
    }
    float kn0 = sqrtf(q0 + 1e-6f), kn1 = sqrtf(q1 + 1e-6f);
    float kn2 = sqrtf(q2 + 1e-6f), kn3 = sqrtf(q3 + 1e-6f);
    float sp0 = softplusf(rstr[b*Rn + 0]);
    float sp1 = softplusf(rstr[b*Rn + 1]);
    float sp2 = softplusf(rstr[b*Rn + 2]);
    float sp3 = softplusf(rstr[b*Rn + 3]);

    // phase A: sharp[r][n] from memory_new rows (warp per row)
    for (int n = wid; n < Nn; n += 32){
        float2 m = ((const float2*)(memory + ((size_t)(b*Nn + n))*Wn))[lane];
        float w = s_ww[n];
        float2 mn;
        mn.x = fmaf(m.x, 1.f - w*ev.x, w*wv.x);
        mn.y = fmaf(m.y, 1.f - w*ev.y, w*wv.y);
        float d0 = mn.x*k0.x + mn.y*k0.y;
        float d1 = mn.x*k1.x + mn.y*k1.y;
        float d2 = mn.x*k2.x + mn.y*k2.y;
        float d3 = mn.x*k3.x + mn.y*k3.y;
        float qq = mn.x*mn.x + mn.y*mn.y;
#pragma unroll
        for (int o = 16; o; o >>= 1){
            d0 += __shfl_xor_sync(0xffffffffu, d0, o);
            d1 += __shfl_xor_sync(0xffffffffu, d1, o);
            d2 += __shfl_xor_sync(0xffffffffu, d2, o);
            d3 += __shfl_xor_sync(0xffffffffu, d3, o);
            qq += __shfl_xor_sync(0xffffffffu, qq, o);
        }
        if (lane == 0){
            float mnorm = sqrtf(qq + 1e-6f);
            s_rw[0][n] = d0 / (kn0 * mnorm + 1e-6f) * sp0;
            s_rw[1][n] = d1 / (kn1 * mnorm + 1e-6f) * sp1;
            s_rw[2][n] = d2 / (kn2 * mnorm + 1e-6f) * sp2;
            s_rw[3][n] = d3 / (kn3 * mnorm + 1e-6f) * sp3;
        }
    }
    __syncthreads();

    // phase B: softmax per r + combine with fwd/bwd via read-mode softmax
    for (int r = 0; r < Rn; r++){
        float v  = s_rw[r][tid];
        float mx = block_reduce_max(v, s_red, &s_b0, lane, wid);
        float e  = expf(v - mx);
        float sm = block_reduce_sum(e, s_red, &s_b1, lane, wid);
        float rc = e / sm;

        float m0v = rmode[(b*Rn + r)*3 + 0];
        float m1v = rmode[(b*Rn + r)*3 + 1];
        float m2v = rmode[(b*Rn + r)*3 + 2];
        float mm = fmaxf(m0v, fmaxf(m1v, m2v));
        float e0 = expf(m0v - mm), e1 = expf(m1v - mm), e2 = expf(m2v - mm);
        float inv = 1.f / (e0 + e1 + e2);
        float bm = e0 * inv, fm = e1 * inv, cm = e2 * inv;

        float rw = cm * rc
                 + fm * g_fwd[(b*Rn + r)*Nn + tid]
                 + bm * g_bwd[(b*Rn + r)*Nn + tid];
        s_rw[r][tid] = rw;
    }
    __syncthreads();

    // phase C: read words
    {
        int z  = tid >> 7;          // 0..7 (splits N)
        int r  = (tid >> 5) & 3;    // 0..3
        int kh = tid & 31;          // 0..31 -> k = 2*kh
        const float* mp = memory + (size_t)(b*Nn)*Wn + kh*2;
        float2 G = make_float2(0.f, 0.f);
        float2 H = make_float2(0.f, 0.f);
        float  S = 0.f;
        int nbase = z * 128;
#pragma unroll 4
        for (int i = 0; i < 128; i++){
            int n = nbase + i;
            float2 m = *(const float2*)(mp + (size_t)n * Wn);
            float rwv = s_rw[r][n];
            float w   = s_ww[n];
            float t2  = rwv * w;
            G.x = fmaf(rwv, m.x, G.x); G.y = fmaf(rwv, m.y, G.y);
            H.x = fmaf(t2,  m.x, H.x); H.y = fmaf(t2,  m.y, H.y);
            S += t2;
        }
        s_G[z][r][kh] = G;
        s_H[z][r][kh] = H;
        if (kh == 0) s_S[z][r] = S;
    }
    __syncthreads();
    if (tid < 128){
        int r2 = tid >> 5, kh2 = tid & 31;
        float gx = 0.f, gy = 0.f, hx = 0.f, hy = 0.f, s = 0.f;
#pragma unroll
        for (int zz = 0; zz < 8; zz++){
            float2 g = s_G[zz][r2][kh2]; gx += g.x; gy += g.y;
            float2 h = s_H[zz][r2][kh2]; hx += h.x; hy += h.y;
            s += s_S[zz][r2];
        }
        float2 e = *(const float2*)(evec + b*Wn + kh2*2);
        float2 w = *(const float2*)(wvec + b*Wn + kh2*2);
        out[(b*Rn + r2)*Wn + kh2*2    ] = gx - e.x*hx + w.x*s;
        out[(b*Rn + r2)*Wn + kh2*2 + 1] = gy - e.y*hy + w.y*s;
    }
}

// ============================================================================
extern "C" void kernel_launch(void* const* d_in, const int* in_sizes, int n_in,
                              void* d_out, int out_size)
{
    const float* memory  = (const float*)d_in[0];
    const float* prw     = (const float*)d_in[1];
    const float* pww     = (const float*)d_in[2];
    const float* pusage  = (const float*)d_in[3];
    const float* plink   = (const float*)d_in[4];
    const float* pprec   = (const float*)d_in[5];
    const float* rkeys   = (const float*)d_in[6];
    const float* rstr    = (const float*)d_in[7];
    const float* wkeys   = (const float*)d_in[8];
    const float* wstr    = (const float*)d_in[9];
    const float* wvec    = (const float*)d_in[10];
    const float* evec    = (const float*)d_in[11];
    const float* fgate   = (const float*)d_in[12];
    const float* agate   = (const float*)d_in[13];
    const float* wgate   = (const float*)d_in[14];
    const float* rmode   = (const float*)d_in[15];
    float* out = (float*)d_out;

    k1_kernel<<<Bn, 1024>>>(memory, prw, pww, pusage, wkeys, wstr,
                            fgate, agate, wgate);
    k2_kernel<<<dim3(16, Bn), 256>>>(plink, prw, pprec);
    k3_kernel<<<Bn, 1024>>>(memory, rkeys, rstr, wvec, evec, rmode, out);
}

// round 7
// speedup vs baseline: 1.5327x; 1.5143x over previous
#include <cuda_runtime.h>
#include <math.h>

#define Bn 64
#define Nn 1024
#define Wn 64
#define Rn 4

typedef unsigned long long u64;

// ---------------- device scratch (no allocations allowed) ----------------
__device__ float g_ww [Bn*Nn];       // new write weights (B,N)
__device__ float g_fwd[Bn*Rn*Nn];    // fwd_w (B,R,N)  fully overwritten by k2
__device__ float g_bwd[Bn*Rn*Nn];    // bwd_w (B,R,N)  atomic-accumulated (zeroed in k1)

__device__ __forceinline__ float softplusf(float x){
    return fmaxf(x, 0.f) + log1pf(expf(-fabsf(x)));
}

// merge step: combine two running sums a,b over lane-pairs at distance d.
// Result at lane l: (hi ? b : a) summed over {l, l^d}; value-index bit = hi.
__device__ __forceinline__ float mstep(float a, float b, int d, bool hi){
    float send = hi ? a : b;
    float recv = __shfl_xor_sync(0xffffffffu, send, d);
    float keep = hi ? b : a;
    return keep + recv;
}

// block reduce helpers (1024 threads / 32 warps)
__device__ __forceinline__ float block_reduce_max(float v, float* s_red, float* s_out,
                                                  int lane, int wid){
#pragma unroll
    for (int o = 16; o; o >>= 1) v = fmaxf(v, __shfl_xor_sync(0xffffffffu, v, o));
    if (lane == 0) s_red[wid] = v;
    __syncthreads();
    if (wid == 0){
        float t = s_red[lane];
#pragma unroll
        for (int o = 16; o; o >>= 1) t = fmaxf(t, __shfl_xor_sync(0xffffffffu, t, o));
        if (lane == 0) *s_out = t;
    }
    __syncthreads();
    return *s_out;
}
__device__ __forceinline__ float block_reduce_sum(float v, float* s_red, float* s_out,
                                                  int lane, int wid){
#pragma unroll
    for (int o = 16; o; o >>= 1) v += __shfl_xor_sync(0xffffffffu, v, o);
    if (lane == 0) s_red[wid] = v;
    __syncthreads();
    if (wid == 0){
        float t = s_red[lane];
#pragma unroll
        for (int o = 16; o; o >>= 1) t += __shfl_xor_sync(0xffffffffu, t, o);
        if (lane == 0) *s_out = t;
    }
    __syncthreads();
    return *s_out;
}

// ============================================================================
// K1: usage, write content softmax, allocation (hybrid bitonic + shfl scan),
//     write_weights -> g_ww; zero g_bwd.  One block/batch, 1024 threads.
// ============================================================================
__global__ void __launch_bounds__(1024) k1_kernel(
    const float* __restrict__ memory,
    const float* __restrict__ prw,
    const float* __restrict__ pww,
    const float* __restrict__ pusage,
    const float* __restrict__ wkeys,
    const float* __restrict__ wstr,
    const float* __restrict__ fgate,
    const float* __restrict__ agate,
    const float* __restrict__ wgate)
{
    int b   = blockIdx.x;
    int tid = threadIdx.x;
    int lane = tid & 31, wid = tid >> 5;

    __shared__ float s_sharp[Nn];
    __shared__ u64   s_key[Nn];
    __shared__ float s_scanw[32];
    __shared__ float s_red[32];
    __shared__ float s_b0, s_b1;

    // ---- usage (register) ----
    float usage;
    {
        float pu = pusage[b*Nn + tid];
        float w0 = pww[b*Nn + tid];
        float u  = pu + (1.f - pu) * w0;
        float phi = 1.f;
#pragma unroll
        for (int r = 0; r < Rn; r++){
            float fg = fgate[b*Rn + r];
            phi *= 1.f - fg * prw[(b*Rn + r)*Nn + tid];
        }
        usage = u * phi;
    }

    // ---- write content: cosine similarity, warp per row ----
    {
        float2 key2 = *(const float2*)(wkeys + b*Wn + lane*2);
        float kn = key2.x*key2.x + key2.y*key2.y;
#pragma unroll
        for (int o = 16; o; o >>= 1) kn += __shfl_xor_sync(0xffffffffu, kn, o);
        kn = sqrtf(kn + 1e-6f);
        float sp = softplusf(wstr[b]);
        for (int n = wid; n < Nn; n += 32){
            float2 m = ((const float2*)(memory + ((size_t)(b*Nn + n))*Wn))[lane];
            float d = key2.x*m.x + key2.y*m.y;
            float q = m.x*m.x + m.y*m.y;
#pragma unroll
            for (int o = 16; o; o >>= 1){
                d += __shfl_xor_sync(0xffffffffu, d, o);
                q += __shfl_xor_sync(0xffffffffu, q, o);
            }
            if (lane == 0){
                float mnorm = sqrtf(q + 1e-6f);
                s_sharp[n] = d / (kn * mnorm + 1e-6f) * sp;
            }
        }
    }
    __syncthreads();

    // ---- softmax over N (content in register) ----
    float content;
    {
        float v  = s_sharp[tid];
        float mx = block_reduce_max(v, s_red, &s_b0, lane, wid);
        float e  = expf(v - mx);
        float sm = block_reduce_sum(e, s_red, &s_b1, lane, wid);
        content = e / sm;
    }

    // ---- allocation: hybrid bitonic sort, descending by packed u64 key ----
    float up   = 1e-6f + (1.f - 1e-6f) * usage;
    float nonu = 1.f - up;                      // in [0,1): positive-float bits monotonic
    u64 key = ((u64)__float_as_uint(nonu) << 32) | (u64)(unsigned)(Nn - 1 - tid);

    s_key[tid] = key;
    for (int k = 2; k <= Nn; k <<= 1){
        int j = k >> 1;
        for (; j >= 32; j >>= 1){              // cross-warp exchange via smem
            __syncthreads();
            u64 other = s_key[tid ^ j];
            bool takeMax = (((tid & k) == 0) == ((tid & j) == 0));
            key = ((other > key) == takeMax) ? other : key;
            __syncthreads();
            s_key[tid] = key;
        }
        for (; j >= 1; j >>= 1){               // intra-warp exchange via shuffle
            u64 other = __shfl_xor_sync(0xffffffffu, key, j);
            bool takeMax = (((tid & k) == 0) == ((tid & j) == 0));
            key = ((other > key) == takeMax) ? other : key;
        }
        s_key[tid] = key;                      // refresh for next stage's smem pass
    }

    // ---- product scan of sorted usage via shuffles ----
    float snon = __uint_as_float((unsigned)(key >> 32));
    int   dest = Nn - 1 - (int)(key & 0xffffffffu);
    float x = 1.f - snon;                      // sorted usage
    float s = x;
#pragma unroll
    for (int o = 1; o <= 16; o <<= 1){
        float t = __shfl_up_sync(0xffffffffu, s, o);
        if (lane >= o) s *= t;
    }
    if (lane == 31) s_scanw[wid] = s;
    __syncthreads();
    if (wid == 0){
        float si = s_scanw[lane];
#pragma unroll
        for (int o = 1; o <= 16; o <<= 1){
            float t = __shfl_up_sync(0xffffffffu, si, o);
            if (lane >= o) si *= t;
        }
        s_scanw[lane] = si;
    }
    __syncthreads();
    float warppre = (wid == 0) ? 1.f : s_scanw[wid - 1];
    float excl = __shfl_up_sync(0xffffffffu, s, 1);
    if (lane == 0) excl = 1.f;
    float salloc = snon * (warppre * excl);

    s_sharp[dest] = salloc;                    // scatter back to original index
    __syncthreads();
    float alloc = s_sharp[tid];

    // ---- write weights ----
    float ag = agate[b], wg = wgate[b];
    g_ww[b*Nn + tid] = wg * (ag * alloc + (1.f - ag) * content);

    // zero bwd scratch (atomics target)
    for (int i = tid; i < Rn*Nn; i += 1024)
        g_bwd[b*Rn*Nn + i] = 0.f;
}

// ============================================================================
// K2: fused link update + fwd/bwd contractions.
//   L[n][m] = (n!=m) * ((1-ww[m]-ww[n])*prev_link[n][m] + ww[n]*prec[m])
//   fwd[r][n] = sum_m prw[r][m]*L[n][m]   (merge-tree reduce, 2-row batches)
//   bwd[r][m] = sum_n prw[r][n]*L[n][m]   (register acc, atomics at end)
// grid (16 row-tiles, 64 batches) x 256 threads; thread owns 4 columns.
// ============================================================================
__global__ void __launch_bounds__(256) k2_kernel(
    const float* __restrict__ link,
    const float* __restrict__ prw,
    const float* __restrict__ prec)
{
    int b  = blockIdx.y;
    int n0 = blockIdx.x * 64;
    int t  = threadIdx.x;
    int lane = t & 31, wid = t >> 5;

    __shared__ float4 s_prw[Nn];       // [n] -> prw[r=0..3][n]
    __shared__ float  s_ww [Nn];
    __shared__ float  s_fwd[64][33];   // padded: conflict-free

    for (int i = t; i < Nn; i += 256){
        float4 p;
        p.x = prw[(b*Rn + 0)*Nn + i];
        p.y = prw[(b*Rn + 1)*Nn + i];
        p.z = prw[(b*Rn + 2)*Nn + i];
        p.w = prw[(b*Rn + 3)*Nn + i];
        s_prw[i] = p;
        s_ww[i]  = g_ww[b*Nn + i];
    }
    __syncthreads();

    int m0 = t * 4;
    float omw[4], pcm[4], pjm[4][4];
#pragma unroll
    for (int j = 0; j < 4; j++){
        omw[j] = 1.f - s_ww[m0 + j];
        float4 pj = s_prw[m0 + j];
        pjm[j][0] = pj.x; pjm[j][1] = pj.y; pjm[j][2] = pj.z; pjm[j][3] = pj.w;
    }
    {
        float4 pc = *(const float4*)(prec + b*Nn + m0);
        pcm[0] = pc.x; pcm[1] = pc.y; pcm[2] = pc.z; pcm[3] = pc.w;
    }

    float bacc[4][4];
#pragma unroll
    for (int r = 0; r < 4; r++)
#pragma unroll
        for (int j = 0; j < 4; j++) bacc[r][j] = 0.f;

    const float4* Lb4 = (const float4*)(link + (size_t)b * Nn * Nn);
    bool h1 = (lane & 1) != 0, h2 = (lane & 2) != 0, h4 = (lane & 4) != 0;

    float4 Pa = __ldcs(Lb4 + (size_t)n0 * 256 + t);
    float4 Pb = __ldcs(Lb4 + (size_t)(n0 + 1) * 256 + t);

    for (int g = 0; g < 32; g++){
        int na = n0 + 2*g;
        float4 Ca = Pa, Cb = Pb;
        if (g < 31){
            Pa = __ldcs(Lb4 + (size_t)(na + 2) * 256 + t);
            Pb = __ldcs(Lb4 + (size_t)(na + 3) * 256 + t);
        }
        float fr[8];
#pragma unroll
        for (int rr = 0; rr < 2; rr++){
            int n = na + rr;
            float4 P = rr ? Cb : Ca;
            float wn = s_ww[n];
            float4 pn = s_prw[n];
            float lk0 = fmaf(omw[0] - wn, P.x, wn * pcm[0]);
            float lk1 = fmaf(omw[1] - wn, P.y, wn * pcm[1]);
            float lk2 = fmaf(omw[2] - wn, P.z, wn * pcm[2]);
            float lk3 = fmaf(omw[3] - wn, P.w, wn * pcm[3]);
            unsigned d = (unsigned)(n - m0);
            if (d == 0u) lk0 = 0.f;
            if (d == 1u) lk1 = 0.f;
            if (d == 2u) lk2 = 0.f;
            if (d == 3u) lk3 = 0.f;
#pragma unroll
            for (int r = 0; r < 4; r++){
                fr[rr*4 + r] = fmaf(pjm[0][r], lk0,
                               fmaf(pjm[1][r], lk1,
                               fmaf(pjm[2][r], lk2, pjm[3][r] * lk3)));
            }
            bacc[0][0] = fmaf(pn.x, lk0, bacc[0][0]);
            bacc[0][1] = fmaf(pn.x, lk1, bacc[0][1]);
            bacc[0][2] = fmaf(pn.x, lk2, bacc[0][2]);
            bacc[0][3] = fmaf(pn.x, lk3, bacc[0][3]);
            bacc[1][0] = fmaf(pn.y, lk0, bacc[1][0]);
            bacc[1][1] = fmaf(pn.y, lk1, bacc[1][1]);
            bacc[1][2] = fmaf(pn.y, lk2, bacc[1][2]);
            bacc[1][3] = fmaf(pn.y, lk3, bacc[1][3]);
            bacc[2][0] = fmaf(pn.z, lk0, bacc[2][0]);
            bacc[2][1] = fmaf(pn.z, lk1, bacc[2][1]);
            bacc[2][2] = fmaf(pn.z, lk2, bacc[2][2]);
            bacc[2][3] = fmaf(pn.z, lk3, bacc[2][3]);
            bacc[3][0] = fmaf(pn.w, lk0, bacc[3][0]);
            bacc[3][1] = fmaf(pn.w, lk1, bacc[3][1]);
            bacc[3][2] = fmaf(pn.w, lk2, bacc[3][2]);
            bacc[3][3] = fmaf(pn.w, lk3, bacc[3][3]);
        }
        // merge-tree reduce: 8 values over 32 lanes in 9 shuffles.
        // value index i = rowbit*4 + r; bits: d=1<->r0, d=2<->r1, d=4<->rowbit.
        float u0 = mstep(fr[0], fr[1], 1, h1);
        float u1 = mstep(fr[2], fr[3], 1, h1);
        float u2 = mstep(fr[4], fr[5], 1, h1);
        float u3 = mstep(fr[6], fr[7], 1, h1);
        float w0 = mstep(u0, u1, 2, h2);
        float w1 = mstep(u2, u3, 2, h2);
        float v  = mstep(w0, w1, 4, h4);
        v += __shfl_xor_sync(0xffffffffu, v, 8);
        v += __shfl_xor_sync(0xffffffffu, v, 16);
        // lane l (<8): v = full warp sum of fr[l&7]
        if (lane < 8)
            s_fwd[2*g + (lane >> 2)][(lane & 3)*8 + wid] = v;
    }
    __syncthreads();

    // fwd final: cross-warp combine (one thread per row,r)
    {
        int nl = t >> 2, r = t & 3;
        float sum = 0.f;
#pragma unroll
        for (int w = 0; w < 8; w++) sum += s_fwd[nl][r*8 + w];
        g_fwd[(b*Rn + r)*Nn + n0 + nl] = sum;
    }

    float* bw = g_bwd + (size_t)b * Rn * Nn;
#pragma unroll
    for (int r = 0; r < 4; r++)
#pragma unroll
        for (int j = 0; j < 4; j++)
            atomicAdd(&bw[r*Nn + m0 + j], bacc[r][j]);
}

// ============================================================================
// K3: memory_new on the fly, read content softmax, mode mix, read words.
// One block per batch, 1024 threads.
// ============================================================================
__global__ void __launch_bounds__(1024) k3_kernel(
    const float* __restrict__ memory,
    const float* __restrict__ rkeys,
    const float* __restrict__ rstr,
    const float* __restrict__ wvec,
    const float* __restrict__ evec,
    const float* __restrict__ rmode,
    float* __restrict__ out)
{
    int b   = blockIdx.x;
    int tid = threadIdx.x;
    int lane = tid & 31, wid = tid >> 5;
    int hl = lane & 15, hh = lane >> 4;

    __shared__ float4 s_rw4[Nn];          // [n] -> rw for r=0..3 (16KB)
    __shared__ float  s_ww[Nn];           // 4KB
    __shared__ float4 s_O[16][4][16];     // z, r, kh (16KB)
    __shared__ float  s_red[32*4];
    __shared__ float  s_bc[8];

    s_ww[tid] = g_ww[b*Nn + tid];
    __syncthreads();

    // per-lane setup (half-warp granularity, float4 over W=64)
    float4 k0 = ((const float4*)(rkeys + (b*Rn + 0)*Wn))[hl];
    float4 k1 = ((const float4*)(rkeys + (b*Rn + 1)*Wn))[hl];
    float4 k2 = ((const float4*)(rkeys + (b*Rn + 2)*Wn))[hl];
    float4 k3 = ((const float4*)(rkeys + (b*Rn + 3)*Wn))[hl];
    float4 ev4 = ((const float4*)(evec + b*Wn))[hl];
    float4 wv4 = ((const float4*)(wvec + b*Wn))[hl];

    float q0 = k0.x*k0.x + k0.y*k0.y + k0.z*k0.z + k0.w*k0.w;
    float q1 = k1.x*k1.x + k1.y*k1.y + k1.z*k1.z + k1.w*k1.w;
    float q2 = k2.x*k2.x + k2.y*k2.y + k2.z*k2.z + k2.w*k2.w;
    float q3 = k3.x*k3.x + k3.y*k3.y + k3.z*k3.z + k3.w*k3.w;
#pragma unroll
    for (int o = 8; o; o >>= 1){
        q0 += __shfl_xor_sync(0xffffffffu, q0, o);
        q1 += __shfl_xor_sync(0xffffffffu, q1, o);
        q2 += __shfl_xor_sync(0xffffffffu, q2, o);
        q3 += __shfl_xor_sync(0xffffffffu, q3, o);
    }
    float kn0 = sqrtf(q0 + 1e-6f), kn1 = sqrtf(q1 + 1e-6f);
    float kn2 = sqrtf(q2 + 1e-6f), kn3 = sqrtf(q3 + 1e-6f);
    int rsel = lane & 3;
    float kn_s = (rsel == 0) ? kn0 : (rsel == 1) ? kn1 : (rsel == 2) ? kn2 : kn3;
    float sp_s = softplusf(rstr[b*Rn + rsel]);
    bool h1 = (lane & 1) != 0, h2 = (lane & 2) != 0;

    // phase A: sharp[r][n], half-warp per row
    for (int it = 0; it < 16; it++){
        int n = it*64 + wid*2 + hh;
        float4 m = ((const float4*)(memory + (size_t)(b*Nn + n)*Wn))[hl];
        float w = s_ww[n];
        float4 mn;
        mn.x = fmaf(m.x, fmaf(-w, ev4.x, 1.f), w*wv4.x);
        mn.y = fmaf(m.y, fmaf(-w, ev4.y, 1.f), w*wv4.y);
        mn.z = fmaf(m.z, fmaf(-w, ev4.z, 1.f), w*wv4.z);
        mn.w = fmaf(m.w, fmaf(-w, ev4.w, 1.f), w*wv4.w);
        float d0 = mn.x*k0.x + mn.y*k0.y + mn.z*k0.z + mn.w*k0.w;
        float d1 = mn.x*k1.x + mn.y*k1.y + mn.z*k1.z + mn.w*k1.w;
        float d2 = mn.x*k2.x + mn.y*k2.y + mn.z*k2.z + mn.w*k2.w;
        float d3 = mn.x*k3.x + mn.y*k3.y + mn.z*k3.z + mn.w*k3.w;
        float qq = mn.x*mn.x + mn.y*mn.y + mn.z*mn.z + mn.w*mn.w;
        // reduce d0..3 over 16 lanes via merges (distances 1,2 then butterflies 4,8)
        float a0 = mstep(d0, d1, 1, h1);
        float a1 = mstep(d2, d3, 1, h1);
        float v  = mstep(a0, a1, 2, h2);
        v += __shfl_xor_sync(0xffffffffu, v, 4);
        v += __shfl_xor_sync(0xffffffffu, v, 8);
        qq += __shfl_xor_sync(0xffffffffu, qq, 8);
        qq += __shfl_xor_sync(0xffffffffu, qq, 4);
        qq += __shfl_xor_sync(0xffffffffu, qq, 2);
        qq += __shfl_xor_sync(0xffffffffu, qq, 1);
        if (hl < 4){
            float mnorm = sqrtf(qq + 1e-6f);
            float sharp = v / (kn_s * mnorm + 1e-6f) * sp_s;
            ((float*)&s_rw4[n])[rsel] = sharp;
        }
    }
    __syncthreads();

    // phase B: 4 softmaxes fused (2 reduction rounds, 4 syncs total)
    {
        float4 v4 = s_rw4[tid];
        float mx0 = v4.x, mx1 = v4.y, mx2 = v4.z, mx3 = v4.w;
#pragma unroll
        for (int o = 16; o; o >>= 1){
            mx0 = fmaxf(mx0, __shfl_xor_sync(0xffffffffu, mx0, o));
            mx1 = fmaxf(mx1, __shfl_xor_sync(0xffffffffu, mx1, o));
            mx2 = fmaxf(mx2, __shfl_xor_sync(0xffffffffu, mx2, o));
            mx3 = fmaxf(mx3, __shfl_xor_sync(0xffffffffu, mx3, o));
        }
        if (lane == 0){
            s_red[wid*4+0] = mx0; s_red[wid*4+1] = mx1;
            s_red[wid*4+2] = mx2; s_red[wid*4+3] = mx3;
        }
        __syncthreads();
        if (wid == 0){
            float t0 = s_red[lane*4+0], t1 = s_red[lane*4+1];
            float t2 = s_red[lane*4+2], t3 = s_red[lane*4+3];
#pragma unroll
            for (int o = 16; o; o >>= 1){
                t0 = fmaxf(t0, __shfl_xor_sync(0xffffffffu, t0, o));
                t1 = fmaxf(t1, __shfl_xor_sync(0xffffffffu, t1, o));
                t2 = fmaxf(t2, __shfl_xor_sync(0xffffffffu, t2, o));
                t3 = fmaxf(t3, __shfl_xor_sync(0xffffffffu, t3, o));
            }
            if (lane == 0){ s_bc[0]=t0; s_bc[1]=t1; s_bc[2]=t2; s_bc[3]=t3; }
        }
        __syncthreads();
        float e0 = expf(v4.x - s_bc[0]);
        float e1 = expf(v4.y - s_bc[1]);
        float e2 = expf(v4.z - s_bc[2]);
        float e3 = expf(v4.w - s_bc[3]);
        float sm0 = e0, sm1 = e1, sm2 = e2, sm3 = e3;
#pragma unroll
        for (int o = 16; o; o >>= 1){
            sm0 += __shfl_xor_sync(0xffffffffu, sm0, o);
            sm1 += __shfl_xor_sync(0xffffffffu, sm1, o);
            sm2 += __shfl_xor_sync(0xffffffffu, sm2, o);
            sm3 += __shfl_xor_sync(0xffffffffu, sm3, o);
        }
        if (lane == 0){
            s_red[wid*4+0] = sm0; s_red[wid*4+1] = sm1;
            s_red[wid*4+2] = sm2; s_red[wid*4+3] = sm3;
        }
        __syncthreads();
        if (wid == 0){
            float t0 = s_red[lane*4+0], t1 = s_red[lane*4+1];
            float t2 = s_red[lane*4+2], t3 = s_red[lane*4+3];
#pragma unroll
            for (int o = 16; o; o >>= 1){
                t0 += __shfl_xor_sync(0xffffffffu, t0, o);
                t1 += __shfl_xor_sync(0xffffffffu, t1, o);
                t2 += __shfl_xor_sync(0xffffffffu, t2, o);
                t3 += __shfl_xor_sync(0xffffffffu, t3, o);
            }
            if (lane == 0){ s_bc[4]=t0; s_bc[5]=t1; s_bc[6]=t2; s_bc[7]=t3; }
        }
        __syncthreads();
        float rw[4];
        float ee[4] = {e0, e1, e2, e3};
#pragma unroll
        for (int r = 0; r < 4; r++){
            float rc = ee[r] / s_bc[4+r];
            float m0v = rmode[(b*Rn + r)*3 + 0];
            float m1v = rmode[(b*Rn + r)*3 + 1];
            float m2v = rmode[(b*Rn + r)*3 + 2];
            float mm = fmaxf(m0v, fmaxf(m1v, m2v));
            float x0 = expf(m0v - mm), x1 = expf(m1v - mm), x2 = expf(m2v - mm);
            float inv = 1.f / (x0 + x1 + x2);
            float bm = x0*inv, fm = x1*inv, cm = x2*inv;
            rw[r] = cm * rc
                  + fm * g_fwd[(b*Rn + r)*Nn + tid]
                  + bm * g_bwd[(b*Rn + r)*Nn + tid];
        }
        s_rw4[tid] = make_float4(rw[0], rw[1], rw[2], rw[3]);
    }
    __syncthreads();

    // phase C: read words. thread = (z, r, kh); per-z fold O = G - e*H + wv*S
    {
        int z  = tid >> 6;
        int r  = (tid >> 4) & 3;
        int kh = tid & 15;
        const float4* mp = (const float4*)(memory + (size_t)b*Nn*Wn) + kh;
        float4 G = make_float4(0.f,0.f,0.f,0.f);
        float4 H = make_float4(0.f,0.f,0.f,0.f);
        float  S = 0.f;
        int nb = z * 64;
#pragma unroll 4
        for (int i = 0; i < 64; i++){
            int n = nb + i;
            float4 m = mp[(size_t)n * 16];
            float rwv = ((const float*)&s_rw4[n])[r];
            float w   = s_ww[n];
            float t2  = rwv * w;
            G.x = fmaf(rwv, m.x, G.x); G.y = fmaf(rwv, m.y, G.y);
            G.z = fmaf(rwv, m.z, G.z); G.w = fmaf(rwv, m.w, G.w);
            H.x = fmaf(t2,  m.x, H.x); H.y = fmaf(t2,  m.y, H.y);
            H.z = fmaf(t2,  m.z, H.z); H.w = fmaf(t2,  m.w, H.w);
            S += t2;
        }
        float4 ef = ((const float4*)(evec + b*Wn))[kh];
        float4 wf = ((const float4*)(wvec + b*Wn))[kh];
        float4 O;
        O.x = fmaf(wf.x, S, fmaf(-ef.x, H.x, G.x));
        O.y = fmaf(wf.y, S, fmaf(-ef.y, H.y, G.y));
        O.z = fmaf(wf.z, S, fmaf(-ef.z, H.z, G.z));
        O.w = fmaf(wf.w, S, fmaf(-ef.w, H.w, G.w));
        s_O[z][r][kh] = O;
    }
    __syncthreads();
    if (tid < 256){
        int r2  = tid >> 6;
        int kh2 = (tid >> 2) & 15;
        int c   = tid & 3;
        float acc = 0.f;
#pragma unroll
        for (int zz = 0; zz < 16; zz++)
            acc += ((const float*)&s_O[zz][r2][kh2])[c];
        out[(b*Rn + r2)*Wn + kh2*4 + c] = acc;
    }
}

// ============================================================================
extern "C" void kernel_launch(void* const* d_in, const int* in_sizes, int n_in,
                              void* d_out, int out_size)
{
    const float* memory  = (const float*)d_in[0];
    const float* prw     = (const float*)d_in[1];
    const float* pww     = (const float*)d_in[2];
    const float* pusage  = (const float*)d_in[3];
    const float* plink   = (const float*)d_in[4];
    const float* pprec   = (const float*)d_in[5];
    const float* rkeys   = (const float*)d_in[6];
    const float* rstr    = (const float*)d_in[7];
    const float* wkeys   = (const float*)d_in[8];
    const float* wstr    = (const float*)d_in[9];
    const float* wvec    = (const float*)d_in[10];
    const float* evec    = (const float*)d_in[11];
    const float* fgate   = (const float*)d_in[12];
    const float* agate   = (const float*)d_in[13];
    const float* wgate   = (const float*)d_in[14];
    const float* rmode   = (const float*)d_in[15];
    float* out = (float*)d_out;

    k1_kernel<<<Bn, 1024>>>(memory, prw, pww, pusage, wkeys, wstr,
                            fgate, agate, wgate);
    k2_kernel<<<dim3(16, Bn), 256>>>(plink, prw, pprec);
    k3_kernel<<<Bn, 1024>>>(memory, rkeys, rstr, wvec, evec, rmode, out);
}

// round 8
// speedup vs baseline: 1.6983x; 1.1080x over previous
#include <cuda_runtime.h>
#include <math.h>

#define Bn 64
#define Nn 1024
#define Wn 64
#define Rn 4
#define NT 16   // k2 row tiles

typedef unsigned long long u64;

// ---------------- device scratch (no allocations allowed) ----------------
__device__ float g_ww  [Bn*Nn];          // new write weights (B,N)
__device__ float g_fwd [Bn*Rn*Nn];       // fwd_w (B,R,N)   fully written by k2
__device__ float g_bwdp[NT][Bn*Rn*Nn];   // bwd partials per row-tile (16MB)

__device__ __forceinline__ float softplusf(float x){
    return fmaxf(x, 0.f) + log1pf(expf(-fabsf(x)));
}

// merge step: combine two running sums a,b over lane-pairs at distance d.
__device__ __forceinline__ float mstep(float a, float b, int d, bool hi){
    float send = hi ? a : b;
    float recv = __shfl_xor_sync(0xffffffffu, send, d);
    float keep = hi ? b : a;
    return keep + recv;
}

// block reduce helpers (1024 threads / 32 warps)
__device__ __forceinline__ float block_reduce_max(float v, float* s_red, float* s_out,
                                                  int lane, int wid){
#pragma unroll
    for (int o = 16; o; o >>= 1) v = fmaxf(v, __shfl_xor_sync(0xffffffffu, v, o));
    if (lane == 0) s_red[wid] = v;
    __syncthreads();
    if (wid == 0){
        float t = s_red[lane];
#pragma unroll
        for (int o = 16; o; o >>= 1) t = fmaxf(t, __shfl_xor_sync(0xffffffffu, t, o));
        if (lane == 0) *s_out = t;
    }
    __syncthreads();
    return *s_out;
}
__device__ __forceinline__ float block_reduce_sum(float v, float* s_red, float* s_out,
                                                  int lane, int wid){
#pragma unroll
    for (int o = 16; o; o >>= 1) v += __shfl_xor_sync(0xffffffffu, v, o);
    if (lane == 0) s_red[wid] = v;
    __syncthreads();
    if (wid == 0){
        float t = s_red[lane];
#pragma unroll
        for (int o = 16; o; o >>= 1) t += __shfl_xor_sync(0xffffffffu, t, o);
        if (lane == 0) *s_out = t;
    }
    __syncthreads();
    return *s_out;
}

// ============================================================================
// K1: usage, write content softmax, allocation (hybrid bitonic + shfl scan),
//     write_weights -> g_ww.  One block/batch, 1024 threads.
// ============================================================================
__global__ void __launch_bounds__(1024) k1_kernel(
    const float* __restrict__ memory,
    const float* __restrict__ prw,
    const float* __restrict__ pww,
    const float* __restrict__ pusage,
    const float* __restrict__ wkeys,
    const float* __restrict__ wstr,
    const float* __restrict__ fgate,
    const float* __restrict__ agate,
    const float* __restrict__ wgate)
{
    int b   = blockIdx.x;
    int tid = threadIdx.x;
    int lane = tid & 31, wid = tid >> 5;
    int hl = lane & 15, hh = lane >> 4;

    __shared__ float s_sharp[Nn];
    __shared__ u64   s_key[Nn];
    __shared__ float s_scanw[32];
    __shared__ float s_red[32];
    __shared__ float s_b0, s_b1;

    // ---- usage (register) ----
    float usage;
    {
        float pu = pusage[b*Nn + tid];
        float w0 = pww[b*Nn + tid];
        float u  = pu + (1.f - pu) * w0;
        float phi = 1.f;
#pragma unroll
        for (int r = 0; r < Rn; r++){
            float fg = fgate[b*Rn + r];
            phi *= 1.f - fg * prw[(b*Rn + r)*Nn + tid];
        }
        usage = u * phi;
    }

    // ---- write content: cosine similarity, half-warp per row, float4 ----
    {
        float4 kq = ((const float4*)(wkeys + b*Wn))[hl];
        float kn = kq.x*kq.x + kq.y*kq.y + kq.z*kq.z + kq.w*kq.w;
#pragma unroll
        for (int o = 8; o; o >>= 1) kn += __shfl_xor_sync(0xffffffffu, kn, o);
        kn = sqrtf(kn + 1e-6f);
        float sp = softplusf(wstr[b]);
        bool h1 = (lane & 1) != 0;
#pragma unroll
        for (int it = 0; it < 16; it++){
            int n = it*64 + wid*2 + hh;
            float4 m = ((const float4*)(memory + (size_t)(b*Nn + n)*Wn))[hl];
            float d = kq.x*m.x + kq.y*m.y + kq.z*m.z + kq.w*m.w;
            float q = m.x*m.x + m.y*m.y + m.z*m.z + m.w*m.w;
            // merge d(q) over 16 lanes: even lanes end with d-sum, odd with q-sum
            float u = mstep(d, q, 1, h1);
            u += __shfl_xor_sync(0xffffffffu, u, 2);
            u += __shfl_xor_sync(0xffffffffu, u, 4);
            u += __shfl_xor_sync(0xffffffffu, u, 8);
            float other = __shfl_xor_sync(0xffffffffu, u, 1);  // q-sum on even lanes
            if (hl == 0){
                float mnorm = sqrtf(other + 1e-6f);
                s_sharp[n] = u / (kn * mnorm + 1e-6f) * sp;
            }
        }
    }
    __syncthreads();

    // ---- softmax over N (content in register) ----
    float content;
    {
        float v  = s_sharp[tid];
        float mx = block_reduce_max(v, s_red, &s_b0, lane, wid);
        float e  = expf(v - mx);
        float sm = block_reduce_sum(e, s_red, &s_b1, lane, wid);
        content = e / sm;
    }

    // ---- allocation: hybrid bitonic sort, descending by packed u64 key ----
    float up   = 1e-6f + (1.f - 1e-6f) * usage;
    float nonu = 1.f - up;                      // positive: float bits monotonic
    u64 key = ((u64)__float_as_uint(nonu) << 32) | (u64)(unsigned)(Nn - 1 - tid);

    s_key[tid] = key;
    for (int k = 2; k <= Nn; k <<= 1){
        int j = k >> 1;
        for (; j >= 32; j >>= 1){              // cross-warp exchange via smem
            __syncthreads();
            u64 other = s_key[tid ^ j];
            bool takeMax = (((tid & k) == 0) == ((tid & j) == 0));
            key = ((other > key) == takeMax) ? other : key;
            __syncthreads();
            s_key[tid] = key;
        }
        for (; j >= 1; j >>= 1){               // intra-warp exchange via shuffle
            u64 other = __shfl_xor_sync(0xffffffffu, key, j);
            bool takeMax = (((tid & k) == 0) == ((tid & j) == 0));
            key = ((other > key) == takeMax) ? other : key;
        }
        s_key[tid] = key;
    }

    // ---- product scan of sorted usage via shuffles ----
    float snon = __uint_as_float((unsigned)(key >> 32));
    int   dest = Nn - 1 - (int)(key & 0xffffffffu);
    float s = 1.f - snon;                      // sorted usage
#pragma unroll
    for (int o = 1; o <= 16; o <<= 1){
        float t = __shfl_up_sync(0xffffffffu, s, o);
        if (lane >= o) s *= t;
    }
    if (lane == 31) s_scanw[wid] = s;
    __syncthreads();
    if (wid == 0){
        float si = s_scanw[lane];
#pragma unroll
        for (int o = 1; o <= 16; o <<= 1){
            float t = __shfl_up_sync(0xffffffffu, si, o);
            if (lane >= o) si *= t;
        }
        s_scanw[lane] = si;
    }
    __syncthreads();
    float warppre = (wid == 0) ? 1.f : s_scanw[wid - 1];
    float excl = __shfl_up_sync(0xffffffffu, s, 1);
    if (lane == 0) excl = 1.f;
    float salloc = snon * (warppre * excl);

    s_sharp[dest] = salloc;                    // scatter back to original index
    __syncthreads();
    float alloc = s_sharp[tid];

    // ---- write weights ----
    float ag = agate[b], wg = wgate[b];
    g_ww[b*Nn + tid] = wg * (ag * alloc + (1.f - ag) * content);
}

// ============================================================================
// K2: fused link update + fwd/bwd contractions. NO atomics, NO in-loop diag.
//   lk(n,m) = (1-ww[m]-ww[n])*P[n][m] + ww[n]*prec[m]   (diag fixed post-loop)
//   fwd[r][n] = sum_m prw[r][m]*lk   (merge-tree reduce, 2-row batches)
//   bwd partial -> g_bwdp[tile]     (register acc, plain STG.128)
// grid (NT row-tiles, 64 batches) x 256 threads; thread owns 4 columns.
// ============================================================================
__global__ void __launch_bounds__(256) k2_kernel(
    const float* __restrict__ link,
    const float* __restrict__ prw,
    const float* __restrict__ prec)
{
    int bx = blockIdx.x;
    int b  = blockIdx.y;
    int n0 = bx * 64;
    int t  = threadIdx.x;
    int lane = t & 31, wid = t >> 5;

    __shared__ float4 s_prw[Nn];       // [n] -> prw[r=0..3][n]
    __shared__ float  s_ww [Nn];
    __shared__ float  s_fwd[64][33];   // padded: conflict-free

    for (int i = t; i < Nn; i += 256){
        float4 p;
        p.x = prw[(b*Rn + 0)*Nn + i];
        p.y = prw[(b*Rn + 1)*Nn + i];
        p.z = prw[(b*Rn + 2)*Nn + i];
        p.w = prw[(b*Rn + 3)*Nn + i];
        s_prw[i] = p;
        s_ww[i]  = g_ww[b*Nn + i];
    }
    __syncthreads();

    int m0 = t * 4;
    float omw[4], pcm[4], pjm[4][4];
#pragma unroll
    for (int j = 0; j < 4; j++){
        omw[j] = 1.f - s_ww[m0 + j];
        float4 pj = s_prw[m0 + j];
        pjm[j][0] = pj.x; pjm[j][1] = pj.y; pjm[j][2] = pj.z; pjm[j][3] = pj.w;
    }
    {
        float4 pc = *(const float4*)(prec + b*Nn + m0);
        pcm[0] = pc.x; pcm[1] = pc.y; pcm[2] = pc.z; pcm[3] = pc.w;
    }

    float bacc[4][4];
#pragma unroll
    for (int r = 0; r < 4; r++)
#pragma unroll
        for (int j = 0; j < 4; j++) bacc[r][j] = 0.f;

    const float4* Lb4 = (const float4*)(link + (size_t)b * Nn * Nn);
    bool h1 = (lane & 1) != 0, h2 = (lane & 2) != 0, h4 = (lane & 4) != 0;

    float4 Pa = __ldcs(Lb4 + (size_t)n0 * 256 + t);
    float4 Pb = __ldcs(Lb4 + (size_t)(n0 + 1) * 256 + t);

    for (int g = 0; g < 32; g++){
        int na = n0 + 2*g;
        float4 Ca = Pa, Cb = Pb;
        if (g < 31){
            Pa = __ldcs(Lb4 + (size_t)(na + 2) * 256 + t);
            Pb = __ldcs(Lb4 + (size_t)(na + 3) * 256 + t);
        }
        float fr[8];
#pragma unroll
        for (int rr = 0; rr < 2; rr++){
            int n = na + rr;
            float4 P = rr ? Cb : Ca;
            float wn = s_ww[n];
            float4 pn = s_prw[n];
            float lk0 = fmaf(omw[0] - wn, P.x, wn * pcm[0]);
            float lk1 = fmaf(omw[1] - wn, P.y, wn * pcm[1]);
            float lk2 = fmaf(omw[2] - wn, P.z, wn * pcm[2]);
            float lk3 = fmaf(omw[3] - wn, P.w, wn * pcm[3]);
#pragma unroll
            for (int r = 0; r < 4; r++){
                fr[rr*4 + r] = fmaf(pjm[0][r], lk0,
                               fmaf(pjm[1][r], lk1,
                               fmaf(pjm[2][r], lk2, pjm[3][r] * lk3)));
            }
            bacc[0][0] = fmaf(pn.x, lk0, bacc[0][0]);
            bacc[0][1] = fmaf(pn.x, lk1, bacc[0][1]);
            bacc[0][2] = fmaf(pn.x, lk2, bacc[0][2]);
            bacc[0][3] = fmaf(pn.x, lk3, bacc[0][3]);
            bacc[1][0] = fmaf(pn.y, lk0, bacc[1][0]);
            bacc[1][1] = fmaf(pn.y, lk1, bacc[1][1]);
            bacc[1][2] = fmaf(pn.y, lk2, bacc[1][2]);
            bacc[1][3] = fmaf(pn.y, lk3, bacc[1][3]);
            bacc[2][0] = fmaf(pn.z, lk0, bacc[2][0]);
            bacc[2][1] = fmaf(pn.z, lk1, bacc[2][1]);
            bacc[2][2] = fmaf(pn.z, lk2, bacc[2][2]);
            bacc[2][3] = fmaf(pn.z, lk3, bacc[2][3]);
            bacc[3][0] = fmaf(pn.w, lk0, bacc[3][0]);
            bacc[3][1] = fmaf(pn.w, lk1, bacc[3][1]);
            bacc[3][2] = fmaf(pn.w, lk2, bacc[3][2]);
            bacc[3][3] = fmaf(pn.w, lk3, bacc[3][3]);
        }
        // merge-tree reduce: 8 values over 32 lanes in 9 shuffles
        float u0 = mstep(fr[0], fr[1], 1, h1);
        float u1 = mstep(fr[2], fr[3], 1, h1);
        float u2 = mstep(fr[4], fr[5], 1, h1);
        float u3 = mstep(fr[6], fr[7], 1, h1);
        float w0 = mstep(u0, u1, 2, h2);
        float w1 = mstep(u2, u3, 2, h2);
        float v  = mstep(w0, w1, 4, h4);
        v += __shfl_xor_sync(0xffffffffu, v, 8);
        v += __shfl_xor_sync(0xffffffffu, v, 16);
        if (lane < 8)
            s_fwd[2*g + (lane >> 2)][(lane & 3)*8 + wid] = v;
    }

    // ---- bwd diagonal correction (only the tile whose rows hit this thread's cols)
    const float* Lb = link + (size_t)b * Nn * Nn;
    if (m0 >= n0 && m0 < n0 + 64){
#pragma unroll
        for (int j = 0; j < 4; j++){
            int m = m0 + j;
            float Pd = Lb[(size_t)m * Nn + m];
            float lkd = fmaf(2.f*omw[j] - 1.f, Pd, (1.f - omw[j]) * pcm[j]);
#pragma unroll
            for (int r = 0; r < 4; r++)
                bacc[r][j] = fmaf(-pjm[j][r], lkd, bacc[r][j]);
        }
    }

    // ---- bwd partial store: coalesced float4, no atomics
    float* bp = g_bwdp[bx] + (size_t)b * Rn * Nn;
#pragma unroll
    for (int r = 0; r < 4; r++)
        *(float4*)(bp + r*Nn + m0) =
            make_float4(bacc[r][0], bacc[r][1], bacc[r][2], bacc[r][3]);

    __syncthreads();

    // ---- fwd final: cross-warp combine + diagonal correction
    {
        int nl = t >> 2, r = t & 3;
        int n  = n0 + nl;
        float sum = 0.f;
#pragma unroll
        for (int w = 0; w < 8; w++) sum += s_fwd[nl][r*8 + w];
        float wwn = s_ww[n];
        float Pd  = Lb[(size_t)n * Nn + n];
        float lkd = fmaf(1.f - 2.f*wwn, Pd, wwn * prec[b*Nn + n]);
        float4 pn = s_prw[n];
        float pr = (r == 0) ? pn.x : (r == 1) ? pn.y : (r == 2) ? pn.z : pn.w;
        g_fwd[(b*Rn + r)*Nn + n] = fmaf(-pr, lkd, sum);
    }
}

// ============================================================================
// K3: memory_new on the fly, read content softmax, mode mix, read words.
// Sums the NT bwd partials inline. One block per batch, 1024 threads.
// ============================================================================
__global__ void __launch_bounds__(1024) k3_kernel(
    const float* __restrict__ memory,
    const float* __restrict__ rkeys,
    const float* __restrict__ rstr,
    const float* __restrict__ wvec,
    const float* __restrict__ evec,
    const float* __restrict__ rmode,
    float* __restrict__ out)
{
    int b   = blockIdx.x;
    int tid = threadIdx.x;
    int lane = tid & 31, wid = tid >> 5;
    int hl = lane & 15, hh = lane >> 4;

    __shared__ float4 s_rw4[Nn];          // [n] -> rw for r=0..3 (16KB)
    __shared__ float  s_ww[Nn];           // 4KB
    __shared__ float4 s_O[16][4][16];     // z, r, kh (16KB)
    __shared__ float  s_red[32*4];
    __shared__ float  s_bc[8];

    s_ww[tid] = g_ww[b*Nn + tid];
    __syncthreads();

    float4 k0 = ((const float4*)(rkeys + (b*Rn + 0)*Wn))[hl];
    float4 k1 = ((const float4*)(rkeys + (b*Rn + 1)*Wn))[hl];
    float4 k2 = ((const float4*)(rkeys + (b*Rn + 2)*Wn))[hl];
    float4 k3 = ((const float4*)(rkeys + (b*Rn + 3)*Wn))[hl];
    float4 ev4 = ((const float4*)(evec + b*Wn))[hl];
    float4 wv4 = ((const float4*)(wvec + b*Wn))[hl];

    float q0 = k0.x*k0.x + k0.y*k0.y + k0.z*k0.z + k0.w*k0.w;
    float q1 = k1.x*k1.x + k1.y*k1.y + k1.z*k1.z + k1.w*k1.w;
    float q2 = k2.x*k2.x + k2.y*k2.y + k2.z*k2.z + k2.w*k2.w;
    float q3 = k3.x*k3.x + k3.y*k3.y + k3.z*k3.z + k3.w*k3.w;
#pragma unroll
    for (int o = 8; o; o >>= 1){
        q0 += __shfl_xor_sync(0xffffffffu, q0, o);
        q1 += __shfl_xor_sync(0xffffffffu, q1, o);
        q2 += __shfl_xor_sync(0xffffffffu, q2, o);
        q3 += __shfl_xor_sync(0xffffffffu, q3, o);
    }
    float kn0 = sqrtf(q0 + 1e-6f), kn1 = sqrtf(q1 + 1e-6f);
    float kn2 = sqrtf(q2 + 1e-6f), kn3 = sqrtf(q3 + 1e-6f);
    int rsel = lane & 3;
    float kn_s = (rsel == 0) ? kn0 : (rsel == 1) ? kn1 : (rsel == 2) ? kn2 : kn3;
    float sp_s = softplusf(rstr[b*Rn + rsel]);
    bool h1 = (lane & 1) != 0, h2 = (lane & 2) != 0;

    // phase A: sharp[r][n], half-warp per row
#pragma unroll 4
    for (int it = 0; it < 16; it++){
        int n = it*64 + wid*2 + hh;
        float4 m = ((const float4*)(memory + (size_t)(b*Nn + n)*Wn))[hl];
        float w = s_ww[n];
        float4 mn;
        mn.x = fmaf(m.x, fmaf(-w, ev4.x, 1.f), w*wv4.x);
        mn.y = fmaf(m.y, fmaf(-w, ev4.y, 1.f), w*wv4.y);
        mn.z = fmaf(m.z, fmaf(-w, ev4.z, 1.f), w*wv4.z);
        mn.w = fmaf(m.w, fmaf(-w, ev4.w, 1.f), w*wv4.w);
        float d0 = mn.x*k0.x + mn.y*k0.y + mn.z*k0.z + mn.w*k0.w;
        float d1 = mn.x*k1.x + mn.y*k1.y + mn.z*k1.z + mn.w*k1.w;
        float d2 = mn.x*k2.x + mn.y*k2.y + mn.z*k2.z + mn.w*k2.w;
        float d3 = mn.x*k3.x + mn.y*k3.y + mn.z*k3.z + mn.w*k3.w;
        float qq = mn.x*mn.x + mn.y*mn.y + mn.z*mn.z + mn.w*mn.w;
        float a0 = mstep(d0, d1, 1, h1);
        float a1 = mstep(d2, d3, 1, h1);
        float v  = mstep(a0, a1, 2, h2);
        v += __shfl_xor_sync(0xffffffffu, v, 4);
        v += __shfl_xor_sync(0xffffffffu, v, 8);
        qq += __shfl_xor_sync(0xffffffffu, qq, 8);
        qq += __shfl_xor_sync(0xffffffffu, qq, 4);
        qq += __shfl_xor_sync(0xffffffffu, qq, 2);
        qq += __shfl_xor_sync(0xffffffffu, qq, 1);
        if (hl < 4){
            float mnorm = sqrtf(qq + 1e-6f);
            float sharp = v / (kn_s * mnorm + 1e-6f) * sp_s;
            ((float*)&s_rw4[n])[rsel] = sharp;
        }
    }
    __syncthreads();

    // phase B: 4 softmaxes fused + mode mix (bwd = sum of NT partials)
    {
        float4 v4 = s_rw4[tid];
        float mx0 = v4.x, mx1 = v4.y, mx2 = v4.z, mx3 = v4.w;
#pragma unroll
        for (int o = 16; o; o >>= 1){
            mx0 = fmaxf(mx0, __shfl_xor_sync(0xffffffffu, mx0, o));
            mx1 = fmaxf(mx1, __shfl_xor_sync(0xffffffffu, mx1, o));
            mx2 = fmaxf(mx2, __shfl_xor_sync(0xffffffffu, mx2, o));
            mx3 = fmaxf(mx3, __shfl_xor_sync(0xffffffffu, mx3, o));
        }
        if (lane == 0){
            s_red[wid*4+0] = mx0; s_red[wid*4+1] = mx1;
            s_red[wid*4+2] = mx2; s_red[wid*4+3] = mx3;
        }
        __syncthreads();
        if (wid == 0){
            float t0 = s_red[lane*4+0], t1 = s_red[lane*4+1];
            float t2 = s_red[lane*4+2], t3 = s_red[lane*4+3];
#pragma unroll
            for (int o = 16; o; o >>= 1){
                t0 = fmaxf(t0, __shfl_xor_sync(0xffffffffu, t0, o));
                t1 = fmaxf(t1, __shfl_xor_sync(0xffffffffu, t1, o));
                t2 = fmaxf(t2, __shfl_xor_sync(0xffffffffu, t2, o));
                t3 = fmaxf(t3, __shfl_xor_sync(0xffffffffu, t3, o));
            }
            if (lane == 0){ s_bc[0]=t0; s_bc[1]=t1; s_bc[2]=t2; s_bc[3]=t3; }
        }
        __syncthreads();
        float e0 = expf(v4.x - s_bc[0]);
        float e1 = expf(v4.y - s_bc[1]);
        float e2 = expf(v4.z - s_bc[2]);
        float e3 = expf(v4.w - s_bc[3]);
        float sm0 = e0, sm1 = e1, sm2 = e2, sm3 = e3;
#pragma unroll
        for (int o = 16; o; o >>= 1){
            sm0 += __shfl_xor_sync(0xffffffffu, sm0, o);
            sm1 += __shfl_xor_sync(0xffffffffu, sm1, o);
            sm2 += __shfl_xor_sync(0xffffffffu, sm2, o);
            sm3 += __shfl_xor_sync(0xffffffffu, sm3, o);
        }
        if (lane == 0){
            s_red[wid*4+0] = sm0; s_red[wid*4+1] = sm1;
            s_red[wid*4+2] = sm2; s_red[wid*4+3] = sm3;
        }
        __syncthreads();
        if (wid == 0){
            float t0 = s_red[lane*4+0], t1 = s_red[lane*4+1];
            float t2 = s_red[lane*4+2], t3 = s_red[lane*4+3];
#pragma unroll
            for (int o = 16; o; o >>= 1){
                t0 += __shfl_xor_sync(0xffffffffu, t0, o);
                t1 += __shfl_xor_sync(0xffffffffu, t1, o);
                t2 += __shfl_xor_sync(0xffffffffu, t2, o);
                t3 += __shfl_xor_sync(0xffffffffu, t3, o);
            }
            if (lane == 0){ s_bc[4]=t0; s_bc[5]=t1; s_bc[6]=t2; s_bc[7]=t3; }
        }
        __syncthreads();
        float rw[4];
        float ee[4] = {e0, e1, e2, e3};
#pragma unroll
        for (int r = 0; r < 4; r++){
            float rc = ee[r] / s_bc[4+r];
            float m0v = rmode[(b*Rn + r)*3 + 0];
            float m1v = rmode[(b*Rn + r)*3 + 1];
            float m2v = rmode[(b*Rn + r)*3 + 2];
            float mm = fmaxf(m0v, fmaxf(m1v, m2v));
            float x0 = expf(m0v - mm), x1 = expf(m1v - mm), x2 = expf(m2v - mm);
            float inv = 1.f / (x0 + x1 + x2);
            float bm = x0*inv, fm = x1*inv, cm = x2*inv;
            float bb = 0.f;
            size_t off = (size_t)(b*Rn + r)*Nn + tid;
#pragma unroll
            for (int tl = 0; tl < NT; tl++)
                bb += g_bwdp[tl][off];
            rw[r] = cm * rc + fm * g_fwd[(b*Rn + r)*Nn + tid] + bm * bb;
        }
        s_rw4[tid] = make_float4(rw[0], rw[1], rw[2], rw[3]);
    }
    __syncthreads();

    // phase C: read words. thread = (z, r, kh); per-z fold O = G - e*H + wv*S
    {
        int z  = tid >> 6;
        int r  = (tid >> 4) & 3;
        int kh = tid & 15;
        const float4* mp = (const float4*)(memory + (size_t)b*Nn*Wn) + kh;
        float4 G = make_float4(0.f,0.f,0.f,0.f);
        float4 H = make_float4(0.f,0.f,0.f,0.f);
        float  S = 0.f;
        int nb = z * 64;
#pragma unroll 4
        for (int i = 0; i < 64; i++){
            int n = nb + i;
            float4 m = mp[(size_t)n * 16];
            float rwv = ((const float*)&s_rw4[n])[r];
            float w   = s_ww[n];
            float t2  = rwv * w;
            G.x = fmaf(rwv, m.x, G.x); G.y = fmaf(rwv, m.y, G.y);
            G.z = fmaf(rwv, m.z, G.z); G.w = fmaf(rwv, m.w, G.w);
            H.x = fmaf(t2,  m.x, H.x); H.y = fmaf(t2,  m.y, H.y);
            H.z = fmaf(t2,  m.z, H.z); H.w = fmaf(t2,  m.w, H.w);
            S += t2;
        }
        float4 ef = ((const float4*)(evec + b*Wn))[kh];
        float4 wf = ((const float4*)(wvec + b*Wn))[kh];
        float4 O;
        O.x = fmaf(wf.x, S, fmaf(-ef.x, H.x, G.x));
        O.y = fmaf(wf.y, S, fmaf(-ef.y, H.y, G.y));
        O.z = fmaf(wf.z, S, fmaf(-ef.z, H.z, G.z));
        O.w = fmaf(wf.w, S, fmaf(-ef.w, H.w, G.w));
        s_O[z][r][kh] = O;
    }
    __syncthreads();
    if (tid < 256){
        int r2  = tid >> 6;
        int kh2 = (tid >> 2) & 15;
        int c   = tid & 3;
        float acc = 0.f;
#pragma unroll
        for (int zz = 0; zz < 16; zz++)
            acc += ((const float*)&s_O[zz][r2][kh2])[c];
        out[(b*Rn + r2)*Wn + kh2*4 + c] = acc;
    }
}

// ============================================================================
extern "C" void kernel_launch(void* const* d_in, const int* in_sizes, int n_in,
                              void* d_out, int out_size)
{
    const float* memory  = (const float*)d_in[0];
    const float* prw     = (const float*)d_in[1];
    const float* pww     = (const float*)d_in[2];
    const float* pusage  = (const float*)d_in[3];
    const float* plink   = (const float*)d_in[4];
    const float* pprec   = (const float*)d_in[5];
    const float* rkeys   = (const float*)d_in[6];
    const float* rstr    = (const float*)d_in[7];
    const float* wkeys   = (const float*)d_in[8];
    const float* wstr    = (const float*)d_in[9];
    const float* wvec    = (const float*)d_in[10];
    const float* evec    = (const float*)d_in[11];
    const float* fgate   = (const float*)d_in[12];
    const float* agate   = (const float*)d_in[13];
    const float* wgate   = (const float*)d_in[14];
    const float* rmode   = (const float*)d_in[15];
    float* out = (float*)d_out;

    k1_kernel<<<Bn, 1024>>>(memory, prw, pww, pusage, wkeys, wstr,
                            fgate, agate, wgate);
    k2_kernel<<<dim3(NT, Bn), 256>>>(plink, prw, pprec);
    k3_kernel<<<Bn, 1024>>>(memory, rkeys, rstr, wvec, evec, rmode, out);
}